// round 3
// baseline (speedup 1.0000x reference)
#include <cuda_runtime.h>
#include <math.h>

// Problem constants
#define BB   8
#define TT   1024
#define HH   768
#define NH   12
#define HS   64
#define H3   2304          // 3*H
#define MROWS (BB*TT)      // 8192

// Scratch (device globals — no allocations allowed)
__device__ float g_qkv[(size_t)MROWS * H3];   // [8192, 2304]
__device__ float g_att[(size_t)MROWS * HH];   // [8192, 768]

// ---------------------------------------------------------------------------
// Tiled SGEMM with bias: C[M,N] = A[M,K] @ B[K,N] + bias[N]
// BM=BN=128, BK=16, 256 threads, 8x8 per thread. Requires M%128==0, N%128==0,
// K%16==0 (true for all our shapes).
// ---------------------------------------------------------------------------
__global__ __launch_bounds__(256) void gemm_bias_kernel(
    const float* __restrict__ A, const float* __restrict__ B,
    const float* __restrict__ bias, float* __restrict__ C,
    int M, int N, int K)
{
    __shared__ float As[16][128];   // As[k][m]
    __shared__ float Bs[16][128];   // Bs[k][n]

    const int tid = threadIdx.x;
    const int bm = blockIdx.y * 128;
    const int bn = blockIdx.x * 128;

    const int arow = tid >> 2;       // 0..63
    const int ac4  = tid & 3;        // 0..3  (k float4 index)
    const int brow = tid >> 5;       // 0..7
    const int bc4  = tid & 31;       // 0..31 (n float4 index)

    const int ty = tid >> 4;         // 0..15
    const int tx = tid & 15;         // 0..15

    float c[8][8];
    #pragma unroll
    for (int i = 0; i < 8; i++)
        #pragma unroll
        for (int j = 0; j < 8; j++) c[i][j] = 0.f;

    for (int k0 = 0; k0 < K; k0 += 16) {
        __syncthreads();   // protect smem from previous iteration's compute
        // Load A tile (128 rows x 16 k), store transposed As[k][m]
        #pragma unroll
        for (int i = 0; i < 2; i++) {
            int row = arow + i * 64;
            float4 v = *(const float4*)(A + (size_t)(bm + row) * K + k0 + ac4 * 4);
            As[ac4 * 4 + 0][row] = v.x;
            As[ac4 * 4 + 1][row] = v.y;
            As[ac4 * 4 + 2][row] = v.z;
            As[ac4 * 4 + 3][row] = v.w;
        }
        // Load B tile (16 k x 128 n)
        #pragma unroll
        for (int i = 0; i < 2; i++) {
            int kr = brow + i * 8;
            *(float4*)&Bs[kr][bc4 * 4] =
                *(const float4*)(B + (size_t)(k0 + kr) * N + bn + bc4 * 4);
        }
        __syncthreads();

        #pragma unroll
        for (int kk = 0; kk < 16; kk++) {
            float a[8], b[8];
            *(float4*)(a)     = *(float4*)&As[kk][ty * 8];
            *(float4*)(a + 4) = *(float4*)&As[kk][ty * 8 + 4];
            *(float4*)(b)     = *(float4*)&Bs[kk][tx * 8];
            *(float4*)(b + 4) = *(float4*)&Bs[kk][tx * 8 + 4];
            #pragma unroll
            for (int i = 0; i < 8; i++)
                #pragma unroll
                for (int j = 0; j < 8; j++)
                    c[i][j] += a[i] * b[j];
        }
    }

    // Epilogue: add bias, store
    #pragma unroll
    for (int i = 0; i < 8; i++) {
        int row = bm + ty * 8 + i;
        #pragma unroll
        for (int j4 = 0; j4 < 2; j4++) {
            int col = bn + tx * 8 + j4 * 4;
            float4 bv = *(const float4*)(bias + col);
            float4 o;
            o.x = c[i][j4 * 4 + 0] + bv.x;
            o.y = c[i][j4 * 4 + 1] + bv.y;
            o.z = c[i][j4 * 4 + 2] + bv.z;
            o.w = c[i][j4 * 4 + 3] + bv.w;
            *(float4*)(C + (size_t)row * N + col) = o;
        }
    }
}

// ---------------------------------------------------------------------------
// Causal flash attention, fp32. One thread = one query row. Block = 128 rows.
// grid = (T/128, NH, B), 128 threads.
// qkv layout: row (b*T + t), 2304 cols: q[0:768) k[768:1536) v[1536:2304)
// ---------------------------------------------------------------------------
__global__ __launch_bounds__(128) void attn_kernel(
    const float* __restrict__ qkv, float* __restrict__ att)
{
    __shared__ float Ks[64][64];
    __shared__ float Vs[64][64];

    const int tid = threadIdx.x;
    const int b = blockIdx.z;
    const int h = blockIdx.y;
    const int qs = blockIdx.x * 128;
    const int r = qs + tid;                 // this thread's query row (0..1023)
    const float scale = 0.125f;             // 1/sqrt(64)

    // Load q row into registers, pre-scaled
    const float* qrow = qkv + (size_t)(b * TT + r) * H3 + h * HS;
    float q[HS];
    #pragma unroll
    for (int i = 0; i < 16; i++) {
        float4 v = ((const float4*)qrow)[i];
        q[i * 4 + 0] = v.x * scale;
        q[i * 4 + 1] = v.y * scale;
        q[i * 4 + 2] = v.z * scale;
        q[i * 4 + 3] = v.w * scale;
    }

    float acc[HS];
    #pragma unroll
    for (int d = 0; d < HS; d++) acc[d] = 0.f;
    float m = -INFINITY, l = 0.f;

    const int ntiles = qs / 64 + 2;         // key tiles covering 0..qs+127

    for (int kt = 0; kt < ntiles; kt++) {
        __syncthreads();   // protect smem from previous tile's compute
        // Cooperatively load K and V tiles (64 rows x 64 dims each)
        const float* kbase = qkv + (size_t)(b * TT + kt * 64) * H3 + HH + h * HS;
        const float* vbase = qkv + (size_t)(b * TT + kt * 64) * H3 + 2 * HH + h * HS;
        #pragma unroll
        for (int i = 0; i < 8; i++) {
            int idx = tid + i * 128;
            int row = idx >> 4;
            int c4  = idx & 15;
            ((float4*)&Ks[row][0])[c4] = *(const float4*)(kbase + (size_t)row * H3 + c4 * 4);
            ((float4*)&Vs[row][0])[c4] = *(const float4*)(vbase + (size_t)row * H3 + c4 * 4);
        }
        __syncthreads();

        const int kidx0 = kt * 64;
        #pragma unroll 1
        for (int cch = 0; cch < 2; cch++) {
            float s[32];
            float cmax = -INFINITY;
            #pragma unroll
            for (int j = 0; j < 32; j++) {
                int kj = kidx0 + cch * 32 + j;
                float dot = 0.f;
                #pragma unroll
                for (int d4 = 0; d4 < 16; d4++) {
                    float4 kv = ((const float4*)&Ks[cch * 32 + j][0])[d4];
                    dot += q[d4 * 4 + 0] * kv.x;
                    dot += q[d4 * 4 + 1] * kv.y;
                    dot += q[d4 * 4 + 2] * kv.z;
                    dot += q[d4 * 4 + 3] * kv.w;
                }
                s[j] = (kj <= r) ? dot : -INFINITY;
                cmax = fmaxf(cmax, s[j]);
            }
            if (cmax == -INFINITY) continue;     // all keys masked for this thread
            float mnew = fmaxf(m, cmax);
            float alpha = __expf(m - mnew);      // m=-inf, mnew finite -> 0
            l *= alpha;
            #pragma unroll
            for (int d = 0; d < HS; d++) acc[d] *= alpha;
            #pragma unroll
            for (int j = 0; j < 32; j++) {
                float p = __expf(s[j] - mnew);   // masked -> exp(-inf) = 0
                l += p;
                #pragma unroll
                for (int d4 = 0; d4 < 16; d4++) {
                    float4 vv = ((const float4*)&Vs[cch * 32 + j][0])[d4];
                    acc[d4 * 4 + 0] += p * vv.x;
                    acc[d4 * 4 + 1] += p * vv.y;
                    acc[d4 * 4 + 2] += p * vv.z;
                    acc[d4 * 4 + 3] += p * vv.w;
                }
            }
            m = mnew;
        }
    }

    const float inv = 1.f / l;
    float* orow = att + (size_t)(b * TT + r) * HH + h * HS;
    #pragma unroll
    for (int d4 = 0; d4 < 16; d4++) {
        float4 o;
        o.x = acc[d4 * 4 + 0] * inv;
        o.y = acc[d4 * 4 + 1] * inv;
        o.z = acc[d4 * 4 + 2] * inv;
        o.w = acc[d4 * 4 + 3] * inv;
        ((float4*)orow)[d4] = o;
    }
}

// ---------------------------------------------------------------------------
// Launch
// ---------------------------------------------------------------------------
extern "C" void kernel_launch(void* const* d_in, const int* in_sizes, int n_in,
                              void* d_out, int out_size)
{
    const float* x      = (const float*)d_in[0];   // [8,1024,768]
    const float* W_attn = (const float*)d_in[1];   // [768,2304]
    const float* b_attn = (const float*)d_in[2];   // [2304]
    const float* W_proj = (const float*)d_in[3];   // [768,768]
    const float* b_proj = (const float*)d_in[4];   // [768]
    float* out = (float*)d_out;                    // [8,1024,768]

    float* qkv;  cudaGetSymbolAddress((void**)&qkv, g_qkv);
    float* attb; cudaGetSymbolAddress((void**)&attb, g_att);

    // 1) QKV projection: [8192,768] @ [768,2304] + b -> g_qkv
    {
        dim3 grid(H3 / 128, MROWS / 128);
        gemm_bias_kernel<<<grid, 256>>>(x, W_attn, b_attn, qkv, MROWS, H3, HH);
    }
    // 2) Causal attention -> g_att
    {
        dim3 grid(TT / 128, NH, BB);
        attn_kernel<<<grid, 128>>>(qkv, attb);
    }
    // 3) Output projection: [8192,768] @ [768,768] + b -> out
    {
        dim3 grid(HH / 128, MROWS / 128);
        gemm_bias_kernel<<<grid, 256>>>(attb, W_proj, b_proj, out, MROWS, HH, HH);
    }
}

// round 7
// speedup vs baseline: 1.4103x; 1.4103x over previous
#include <cuda_runtime.h>
#include <cstdint>
#include <math.h>

// Problem constants
#define BB   8
#define TT   1024
#define HH   768
#define NH   12
#define HS   64
#define H3   2304          // 3*H
#define MROWS (BB*TT)      // 8192

// Scratch (device globals — no allocations allowed)
__device__ float g_qkv[(size_t)MROWS * H3];   // [8192, 2304]
__device__ float g_att[(size_t)MROWS * HH];   // [8192, 768]

// ---------------------------------------------------------------------------
// tf32 helpers (arch-generic PTX; NO tcgen05 — harness lowers via compute_103
// which rejects all sm_103a-gated instructions)
// ---------------------------------------------------------------------------
__device__ __forceinline__ float to_tf32(float x) {
    float y;
    asm("cvt.rna.tf32.f32 %0, %1;" : "=f"(y) : "f"(x));
    return y;
}

__device__ __forceinline__ void mma1688(float* d, const uint32_t* a, const uint32_t* b) {
    asm volatile(
        "mma.sync.aligned.m16n8k8.row.col.f32.tf32.tf32.f32 "
        "{%0,%1,%2,%3}, {%4,%5,%6,%7}, {%8,%9}, {%0,%1,%2,%3};"
        : "+f"(d[0]), "+f"(d[1]), "+f"(d[2]), "+f"(d[3])
        : "r"(a[0]), "r"(a[1]), "r"(a[2]), "r"(a[3]),
          "r"(b[0]), "r"(b[1]));
}

// ===========================================================================
// Warp-MMA tf32 GEMM with bias: C[M,N] = A[M,K] @ B[K,N] + bias[N]
// BM=128, BN=128, BK=32, 256 threads = 8 warps (4 m x 2 n), warp tile 32x64.
// Requires M%128==0, N%128==0, K%32==0 (true for all our shapes).
// ===========================================================================
#define AP 129   // As row pitch (floats): [32 k][128 m] transposed
#define BP 132   // Bs row pitch (floats): [32 k][128 n]

__global__ __launch_bounds__(256, 2) void gemm_mma_kernel(
    const float* __restrict__ A, const float* __restrict__ B,
    const float* __restrict__ bias, float* __restrict__ C,
    int M, int N, int K)
{
    __shared__ float As[32 * AP];
    __shared__ float Bs[32 * BP];

    const int tid = threadIdx.x;
    const int wid = tid >> 5;
    const int lane = tid & 31;
    const int g   = lane >> 2;      // groupID 0..7
    const int tig = lane & 3;       // thread-in-group 0..3
    const int wm = wid & 3;         // warp m index 0..3
    const int wn = wid >> 2;        // warp n index 0..1
    const int bm = blockIdx.y * 128;
    const int bn = blockIdx.x * 128;

    float d[2][8][4];
    #pragma unroll
    for (int mt = 0; mt < 2; mt++)
        #pragma unroll
        for (int nt = 0; nt < 8; nt++)
            #pragma unroll
            for (int r = 0; r < 4; r++) d[mt][nt][r] = 0.f;

    const int a_m  = tid >> 3;      // 0..31 (+32 per i)
    const int a_c4 = tid & 7;       // float4 index within 32-float row
    const int b_k  = tid >> 5;      // 0..7 (+8 per i)
    const int b_n4 = lane;          // 0..31 float4 index

    const int nit = K >> 5;
    for (int kc = 0; kc < nit; kc++) {
        __syncthreads();   // previous compute done before overwriting smem
        // A tile: [128 m][32 k] -> As[k][m] transposed, tf32-rounded
        #pragma unroll
        for (int i = 0; i < 4; i++) {
            int m = a_m + i * 32;
            float4 v = *(const float4*)(A + (size_t)(bm + m) * K + kc * 32 + a_c4 * 4);
            As[(a_c4 * 4 + 0) * AP + m] = to_tf32(v.x);
            As[(a_c4 * 4 + 1) * AP + m] = to_tf32(v.y);
            As[(a_c4 * 4 + 2) * AP + m] = to_tf32(v.z);
            As[(a_c4 * 4 + 3) * AP + m] = to_tf32(v.w);
        }
        // B tile: [32 k][128 n] -> Bs[k][n], tf32-rounded
        #pragma unroll
        for (int i = 0; i < 4; i++) {
            int k = b_k + i * 8;
            float4 v = *(const float4*)(B + (size_t)(kc * 32 + k) * N + bn + b_n4 * 4);
            float4 w;
            w.x = to_tf32(v.x); w.y = to_tf32(v.y);
            w.z = to_tf32(v.z); w.w = to_tf32(v.w);
            *(float4*)&Bs[k * BP + b_n4 * 4] = w;
        }
        __syncthreads();

        #pragma unroll
        for (int ks = 0; ks < 4; ks++) {
            const int k0 = ks * 8;
            // A fragments: 2 m-tiles
            uint32_t af[2][4];
            #pragma unroll
            for (int mt = 0; mt < 2; mt++) {
                int mrow = wm * 32 + mt * 16 + g;
                af[mt][0] = __float_as_uint(As[(k0 + tig) * AP + mrow]);
                af[mt][1] = __float_as_uint(As[(k0 + tig) * AP + mrow + 8]);
                af[mt][2] = __float_as_uint(As[(k0 + tig + 4) * AP + mrow]);
                af[mt][3] = __float_as_uint(As[(k0 + tig + 4) * AP + mrow + 8]);
            }
            // B fragments: 8 n-tiles
            uint32_t bf[8][2];
            #pragma unroll
            for (int nt = 0; nt < 8; nt++) {
                int ncol = wn * 64 + nt * 8 + g;
                bf[nt][0] = __float_as_uint(Bs[(k0 + tig) * BP + ncol]);
                bf[nt][1] = __float_as_uint(Bs[(k0 + tig + 4) * BP + ncol]);
            }
            #pragma unroll
            for (int mt = 0; mt < 2; mt++)
                #pragma unroll
                for (int nt = 0; nt < 8; nt++)
                    mma1688(d[mt][nt], af[mt], bf[nt]);
        }
    }

    // Epilogue: bias add + store (float2 per c-pair)
    #pragma unroll
    for (int mt = 0; mt < 2; mt++) {
        int r0 = bm + wm * 32 + mt * 16 + g;
        #pragma unroll
        for (int nt = 0; nt < 8; nt++) {
            int c0 = bn + wn * 64 + nt * 8 + tig * 2;
            float bx = bias[c0], by = bias[c0 + 1];
            float2 o0 = make_float2(d[mt][nt][0] + bx, d[mt][nt][1] + by);
            float2 o1 = make_float2(d[mt][nt][2] + bx, d[mt][nt][3] + by);
            *(float2*)(C + (size_t)r0 * N + c0)       = o0;
            *(float2*)(C + (size_t)(r0 + 8) * N + c0) = o1;
        }
    }
}

// ---------------------------------------------------------------------------
// Causal flash attention, fp32. One thread = one query row. Block = 128 rows.
// grid = (T/128, NH, B), 128 threads. (unchanged — R2-proven)
// ---------------------------------------------------------------------------
__global__ __launch_bounds__(128) void attn_kernel(
    const float* __restrict__ qkv, float* __restrict__ att)
{
    __shared__ float Ks[64][64];
    __shared__ float Vs[64][64];

    const int tid = threadIdx.x;
    const int b = blockIdx.z;
    const int h = blockIdx.y;
    const int qs = blockIdx.x * 128;
    const int r = qs + tid;
    const float scale = 0.125f;

    const float* qrow = qkv + (size_t)(b * TT + r) * H3 + h * HS;
    float q[HS];
    #pragma unroll
    for (int i = 0; i < 16; i++) {
        float4 v = ((const float4*)qrow)[i];
        q[i * 4 + 0] = v.x * scale;
        q[i * 4 + 1] = v.y * scale;
        q[i * 4 + 2] = v.z * scale;
        q[i * 4 + 3] = v.w * scale;
    }

    float acc[HS];
    #pragma unroll
    for (int d = 0; d < HS; d++) acc[d] = 0.f;
    float m = -INFINITY, l = 0.f;

    const int ntiles = qs / 64 + 2;

    for (int kt = 0; kt < ntiles; kt++) {
        __syncthreads();
        const float* kbase = qkv + (size_t)(b * TT + kt * 64) * H3 + HH + h * HS;
        const float* vbase = qkv + (size_t)(b * TT + kt * 64) * H3 + 2 * HH + h * HS;
        #pragma unroll
        for (int i = 0; i < 8; i++) {
            int idx = tid + i * 128;
            int row = idx >> 4;
            int c4  = idx & 15;
            ((float4*)&Ks[row][0])[c4] = *(const float4*)(kbase + (size_t)row * H3 + c4 * 4);
            ((float4*)&Vs[row][0])[c4] = *(const float4*)(vbase + (size_t)row * H3 + c4 * 4);
        }
        __syncthreads();

        const int kidx0 = kt * 64;
        #pragma unroll 1
        for (int cch = 0; cch < 2; cch++) {
            float s[32];
            float cmax = -INFINITY;
            #pragma unroll
            for (int j = 0; j < 32; j++) {
                int kj = kidx0 + cch * 32 + j;
                float dot = 0.f;
                #pragma unroll
                for (int d4 = 0; d4 < 16; d4++) {
                    float4 kv = ((const float4*)&Ks[cch * 32 + j][0])[d4];
                    dot += q[d4 * 4 + 0] * kv.x;
                    dot += q[d4 * 4 + 1] * kv.y;
                    dot += q[d4 * 4 + 2] * kv.z;
                    dot += q[d4 * 4 + 3] * kv.w;
                }
                s[j] = (kj <= r) ? dot : -INFINITY;
                cmax = fmaxf(cmax, s[j]);
            }
            if (cmax == -INFINITY) continue;
            float mnew = fmaxf(m, cmax);
            float alpha = __expf(m - mnew);
            l *= alpha;
            #pragma unroll
            for (int d = 0; d < HS; d++) acc[d] *= alpha;
            #pragma unroll
            for (int j = 0; j < 32; j++) {
                float p = __expf(s[j] - mnew);
                l += p;
                #pragma unroll
                for (int d4 = 0; d4 < 16; d4++) {
                    float4 vv = ((const float4*)&Vs[cch * 32 + j][0])[d4];
                    acc[d4 * 4 + 0] += p * vv.x;
                    acc[d4 * 4 + 1] += p * vv.y;
                    acc[d4 * 4 + 2] += p * vv.z;
                    acc[d4 * 4 + 3] += p * vv.w;
                }
            }
            m = mnew;
        }
    }

    const float inv = 1.f / l;
    float* orow = att + (size_t)(b * TT + r) * HH + h * HS;
    #pragma unroll
    for (int d4 = 0; d4 < 16; d4++) {
        float4 o;
        o.x = acc[d4 * 4 + 0] * inv;
        o.y = acc[d4 * 4 + 1] * inv;
        o.z = acc[d4 * 4 + 2] * inv;
        o.w = acc[d4 * 4 + 3] * inv;
        ((float4*)orow)[d4] = o;
    }
}

// ---------------------------------------------------------------------------
// Launch
// ---------------------------------------------------------------------------
extern "C" void kernel_launch(void* const* d_in, const int* in_sizes, int n_in,
                              void* d_out, int out_size)
{
    const float* x      = (const float*)d_in[0];   // [8,1024,768]
    const float* W_attn = (const float*)d_in[1];   // [768,2304]
    const float* b_attn = (const float*)d_in[2];   // [2304]
    const float* W_proj = (const float*)d_in[3];   // [768,768]
    const float* b_proj = (const float*)d_in[4];   // [768]
    float* out = (float*)d_out;                    // [8,1024,768]

    float* qkv;  cudaGetSymbolAddress((void**)&qkv, g_qkv);
    float* attb; cudaGetSymbolAddress((void**)&attb, g_att);

    // 1) QKV projection: [8192,768] @ [768,2304] + b -> g_qkv  (tf32 mma.sync)
    {
        dim3 grid(H3 / 128, MROWS / 128);
        gemm_mma_kernel<<<grid, 256>>>(x, W_attn, b_attn, qkv, MROWS, H3, HH);
    }
    // 2) Causal attention -> g_att
    {
        dim3 grid(TT / 128, NH, BB);
        attn_kernel<<<grid, 128>>>(qkv, attb);
    }
    // 3) Output projection: [8192,768] @ [768,768] + b -> out  (tf32 mma.sync)
    {
        dim3 grid(HH / 128, MROWS / 128);
        gemm_mma_kernel<<<grid, 256>>>(attb, W_proj, b_proj, out, MROWS, HH, HH);
    }
}

// round 9
// speedup vs baseline: 2.8077x; 1.9908x over previous
#include <cuda_runtime.h>
#include <cstdint>
#include <math.h>

// Problem constants
#define BB   8
#define TT   1024
#define HH   768
#define NH   12
#define HS   64
#define H3   2304          // 3*H
#define MROWS (BB*TT)      // 8192

// Scratch (device globals — no allocations allowed)
__device__ float g_qkv[(size_t)MROWS * H3];   // [8192, 2304]
__device__ float g_att[(size_t)MROWS * HH];   // [8192, 768]

// ---------------------------------------------------------------------------
// tf32 helpers (arch-generic PTX; NO tcgen05 — harness lowers via compute_103
// which rejects all sm_103a-gated instructions)
// ---------------------------------------------------------------------------
__device__ __forceinline__ float to_tf32(float x) {
    float y;
    asm("cvt.rna.tf32.f32 %0, %1;" : "=f"(y) : "f"(x));
    return y;
}

__device__ __forceinline__ void mma1688(float* d, const uint32_t* a, const uint32_t* b) {
    asm volatile(
        "mma.sync.aligned.m16n8k8.row.col.f32.tf32.tf32.f32 "
        "{%0,%1,%2,%3}, {%4,%5,%6,%7}, {%8,%9}, {%0,%1,%2,%3};"
        : "+f"(d[0]), "+f"(d[1]), "+f"(d[2]), "+f"(d[3])
        : "r"(a[0]), "r"(a[1]), "r"(a[2]), "r"(a[3]),
          "r"(b[0]), "r"(b[1]));
}

// ===========================================================================
// Warp-MMA tf32 GEMM with bias: C[M,N] = A[M,K] @ B[K,N] + bias[N]
// BM=128, BN=128, BK=32, 256 threads = 8 warps (4 m x 2 n), warp tile 32x64.
// (unchanged from R7 — proven at 98 TF/s)
// ===========================================================================
#define AP 129   // As row pitch (floats): [32 k][128 m] transposed
#define BP 132   // Bs row pitch (floats): [32 k][128 n]

__global__ __launch_bounds__(256, 2) void gemm_mma_kernel(
    const float* __restrict__ A, const float* __restrict__ B,
    const float* __restrict__ bias, float* __restrict__ C,
    int M, int N, int K)
{
    __shared__ float As[32 * AP];
    __shared__ float Bs[32 * BP];

    const int tid = threadIdx.x;
    const int wid = tid >> 5;
    const int lane = tid & 31;
    const int g   = lane >> 2;
    const int tig = lane & 3;
    const int wm = wid & 3;
    const int wn = wid >> 2;
    const int bm = blockIdx.y * 128;
    const int bn = blockIdx.x * 128;

    float d[2][8][4];
    #pragma unroll
    for (int mt = 0; mt < 2; mt++)
        #pragma unroll
        for (int nt = 0; nt < 8; nt++)
            #pragma unroll
            for (int r = 0; r < 4; r++) d[mt][nt][r] = 0.f;

    const int a_m  = tid >> 3;
    const int a_c4 = tid & 7;
    const int b_k  = tid >> 5;
    const int b_n4 = lane;

    const int nit = K >> 5;
    for (int kc = 0; kc < nit; kc++) {
        __syncthreads();
        #pragma unroll
        for (int i = 0; i < 4; i++) {
            int m = a_m + i * 32;
            float4 v = *(const float4*)(A + (size_t)(bm + m) * K + kc * 32 + a_c4 * 4);
            As[(a_c4 * 4 + 0) * AP + m] = to_tf32(v.x);
            As[(a_c4 * 4 + 1) * AP + m] = to_tf32(v.y);
            As[(a_c4 * 4 + 2) * AP + m] = to_tf32(v.z);
            As[(a_c4 * 4 + 3) * AP + m] = to_tf32(v.w);
        }
        #pragma unroll
        for (int i = 0; i < 4; i++) {
            int k = b_k + i * 8;
            float4 v = *(const float4*)(B + (size_t)(kc * 32 + k) * N + bn + b_n4 * 4);
            float4 w;
            w.x = to_tf32(v.x); w.y = to_tf32(v.y);
            w.z = to_tf32(v.z); w.w = to_tf32(v.w);
            *(float4*)&Bs[k * BP + b_n4 * 4] = w;
        }
        __syncthreads();

        #pragma unroll
        for (int ks = 0; ks < 4; ks++) {
            const int k0 = ks * 8;
            uint32_t af[2][4];
            #pragma unroll
            for (int mt = 0; mt < 2; mt++) {
                int mrow = wm * 32 + mt * 16 + g;
                af[mt][0] = __float_as_uint(As[(k0 + tig) * AP + mrow]);
                af[mt][1] = __float_as_uint(As[(k0 + tig) * AP + mrow + 8]);
                af[mt][2] = __float_as_uint(As[(k0 + tig + 4) * AP + mrow]);
                af[mt][3] = __float_as_uint(As[(k0 + tig + 4) * AP + mrow + 8]);
            }
            uint32_t bf[8][2];
            #pragma unroll
            for (int nt = 0; nt < 8; nt++) {
                int ncol = wn * 64 + nt * 8 + g;
                bf[nt][0] = __float_as_uint(Bs[(k0 + tig) * BP + ncol]);
                bf[nt][1] = __float_as_uint(Bs[(k0 + tig + 4) * BP + ncol]);
            }
            #pragma unroll
            for (int mt = 0; mt < 2; mt++)
                #pragma unroll
                for (int nt = 0; nt < 8; nt++)
                    mma1688(d[mt][nt], af[mt], bf[nt]);
        }
    }

    #pragma unroll
    for (int mt = 0; mt < 2; mt++) {
        int r0 = bm + wm * 32 + mt * 16 + g;
        #pragma unroll
        for (int nt = 0; nt < 8; nt++) {
            int c0 = bn + wn * 64 + nt * 8 + tig * 2;
            float bx = bias[c0], by = bias[c0 + 1];
            float2 o0 = make_float2(d[mt][nt][0] + bx, d[mt][nt][1] + by);
            float2 o1 = make_float2(d[mt][nt][2] + bx, d[mt][nt][3] + by);
            *(float2*)(C + (size_t)r0 * N + c0)       = o0;
            *(float2*)(C + (size_t)(r0 + 8) * N + c0) = o1;
        }
    }
}

// ===========================================================================
// Causal flash attention via tf32 mma.sync.
// Block = 128 threads (4 warps), Q tile = 64 rows (16/warp), K/V tile = 64.
// grid = (T/64, NH, B). Only kt <= qt tiles; diagonal tile element-masked.
//   Ks pitch 68: B-frag banks 4g+tig (conflict-free); Q stages through Ks.
//   Vs pitch 72: B-frag banks 8tig+g (conflict-free).
// P converted C-layout -> A-layout in-register via shfl (no smem round trip).
// ===========================================================================
#define KP 68
#define VP 72

__global__ __launch_bounds__(128, 3) void attn_mma_kernel(
    const float* __restrict__ qkv, float* __restrict__ att)
{
    __shared__ float Ks[64][KP];   // K tile; also stages Q at start
    __shared__ float Vs[64][VP];   // V tile

    const int tid  = threadIdx.x;
    const int wid  = tid >> 5;
    const int lane = tid & 31;
    const int g    = lane >> 2;
    const int tig  = lane & 3;
    const int b    = blockIdx.z;
    const int h    = blockIdx.y;
    const int qt   = blockIdx.x;        // q tile index 0..15
    const int qs   = qt * 64;

    // ---- Stage Q tile (scaled by 1/8, tf32-rounded) into Ks buffer ----
    {
        const float* qb = qkv + (size_t)(b * TT + qs) * H3 + h * HS;
        #pragma unroll
        for (int i = 0; i < 8; i++) {
            int idx = tid + i * 128;
            int r = idx >> 4, c4 = idx & 15;
            float4 v = *(const float4*)(qb + (size_t)r * H3 + c4 * 4);
            float4 w;
            w.x = to_tf32(v.x * 0.125f); w.y = to_tf32(v.y * 0.125f);
            w.z = to_tf32(v.z * 0.125f); w.w = to_tf32(v.w * 0.125f);
            *(float4*)&Ks[r][c4 * 4] = w;
        }
    }
    __syncthreads();

    // ---- Extract Q fragments to registers (A-layout, m16k8 per k-step) ----
    uint32_t af[8][4];
    {
        const int r0 = wid * 16 + g;
        #pragma unroll
        for (int ks = 0; ks < 8; ks++) {
            af[ks][0] = __float_as_uint(Ks[r0][ks * 8 + tig]);
            af[ks][1] = __float_as_uint(Ks[r0 + 8][ks * 8 + tig]);
            af[ks][2] = __float_as_uint(Ks[r0][ks * 8 + tig + 4]);
            af[ks][3] = __float_as_uint(Ks[r0 + 8][ks * 8 + tig + 4]);
        }
    }

    float O[8][4];
    #pragma unroll
    for (int nt = 0; nt < 8; nt++)
        #pragma unroll
        for (int r = 0; r < 4; r++) O[nt][r] = 0.f;
    float m0 = -INFINITY, m1 = -INFINITY, l0 = 0.f, l1 = 0.f;
    const int row0 = qs + wid * 16 + g;     // global q rows this thread owns
    const int row1 = row0 + 8;

    const int s0l = (lane & ~3) | (tig >> 1);   // shfl source lanes for P conversion
    const int s1l = s0l + 2;
    const bool todd = (tig & 1);

    for (int kt = 0; kt <= qt; kt++) {
        __syncthreads();    // prior compute / Q extraction done before overwrite
        // ---- Stage K and V tiles (tf32-rounded) ----
        const float* kb = qkv + (size_t)(b * TT + kt * 64) * H3 + HH + h * HS;
        const float* vb = kb + HH;
        #pragma unroll
        for (int i = 0; i < 8; i++) {
            int idx = tid + i * 128;
            int r = idx >> 4, c4 = idx & 15;
            float4 v = *(const float4*)(kb + (size_t)r * H3 + c4 * 4);
            float4 w;
            w.x = to_tf32(v.x); w.y = to_tf32(v.y);
            w.z = to_tf32(v.z); w.w = to_tf32(v.w);
            *(float4*)&Ks[r][c4 * 4] = w;
            float4 u = *(const float4*)(vb + (size_t)r * H3 + c4 * 4);
            float4 z;
            z.x = to_tf32(u.x); z.y = to_tf32(u.y);
            z.z = to_tf32(u.z); z.w = to_tf32(u.w);
            *(float4*)&Vs[r][c4 * 4] = z;
        }
        __syncthreads();

        // ---- S = Q @ K^T  (16 rows x 64 keys per warp) ----
        float S[8][4];
        #pragma unroll
        for (int nt = 0; nt < 8; nt++)
            #pragma unroll
            for (int r = 0; r < 4; r++) S[nt][r] = 0.f;
        #pragma unroll
        for (int ks = 0; ks < 8; ks++) {
            #pragma unroll
            for (int nt = 0; nt < 8; nt++) {
                uint32_t bf[2];
                bf[0] = __float_as_uint(Ks[nt * 8 + g][ks * 8 + tig]);
                bf[1] = __float_as_uint(Ks[nt * 8 + g][ks * 8 + tig + 4]);
                mma1688(S[nt], af[ks], bf);
            }
        }

        // ---- Causal mask (diagonal tile only) ----
        if (kt == qt) {
            #pragma unroll
            for (int nt = 0; nt < 8; nt++) {
                int c0 = kt * 64 + nt * 8 + 2 * tig;
                if (c0     > row0) S[nt][0] = -INFINITY;
                if (c0 + 1 > row0) S[nt][1] = -INFINITY;
                if (c0     > row1) S[nt][2] = -INFINITY;
                if (c0 + 1 > row1) S[nt][3] = -INFINITY;
            }
        }

        // ---- Online softmax ----
        float tm0 = -INFINITY, tm1 = -INFINITY;
        #pragma unroll
        for (int nt = 0; nt < 8; nt++) {
            tm0 = fmaxf(tm0, fmaxf(S[nt][0], S[nt][1]));
            tm1 = fmaxf(tm1, fmaxf(S[nt][2], S[nt][3]));
        }
        tm0 = fmaxf(tm0, __shfl_xor_sync(0xffffffffu, tm0, 1));
        tm0 = fmaxf(tm0, __shfl_xor_sync(0xffffffffu, tm0, 2));
        tm1 = fmaxf(tm1, __shfl_xor_sync(0xffffffffu, tm1, 1));
        tm1 = fmaxf(tm1, __shfl_xor_sync(0xffffffffu, tm1, 2));

        float mn0 = fmaxf(m0, tm0), mn1 = fmaxf(m1, tm1);
        float al0 = __expf(m0 - mn0), al1 = __expf(m1 - mn1);
        m0 = mn0; m1 = mn1;

        float rs0 = 0.f, rs1 = 0.f;
        uint32_t P[8][4];
        #pragma unroll
        for (int nt = 0; nt < 8; nt++) {
            float p0 = __expf(S[nt][0] - mn0);
            float p1 = __expf(S[nt][1] - mn0);
            float p2 = __expf(S[nt][2] - mn1);
            float p3 = __expf(S[nt][3] - mn1);
            rs0 += p0 + p1;
            rs1 += p2 + p3;
            P[nt][0] = __float_as_uint(to_tf32(p0));
            P[nt][1] = __float_as_uint(to_tf32(p1));
            P[nt][2] = __float_as_uint(to_tf32(p2));
            P[nt][3] = __float_as_uint(to_tf32(p3));
        }
        rs0 += __shfl_xor_sync(0xffffffffu, rs0, 1);
        rs0 += __shfl_xor_sync(0xffffffffu, rs0, 2);
        rs1 += __shfl_xor_sync(0xffffffffu, rs1, 1);
        rs1 += __shfl_xor_sync(0xffffffffu, rs1, 2);
        l0 = l0 * al0 + rs0;
        l1 = l1 * al1 + rs1;

        #pragma unroll
        for (int nt = 0; nt < 8; nt++) {
            O[nt][0] *= al0; O[nt][1] *= al0;
            O[nt][2] *= al1; O[nt][3] *= al1;
        }

        // ---- O += P @ V ----
        #pragma unroll
        for (int ks = 0; ks < 8; ks++) {
            // Convert P C-layout (cols 2tig,2tig+1) -> A-layout (cols tig,tig+4)
            uint32_t t00 = __shfl_sync(0xffffffffu, P[ks][0], s0l);
            uint32_t t01 = __shfl_sync(0xffffffffu, P[ks][1], s0l);
            uint32_t t10 = __shfl_sync(0xffffffffu, P[ks][2], s0l);
            uint32_t t11 = __shfl_sync(0xffffffffu, P[ks][3], s0l);
            uint32_t u00 = __shfl_sync(0xffffffffu, P[ks][0], s1l);
            uint32_t u01 = __shfl_sync(0xffffffffu, P[ks][1], s1l);
            uint32_t u10 = __shfl_sync(0xffffffffu, P[ks][2], s1l);
            uint32_t u11 = __shfl_sync(0xffffffffu, P[ks][3], s1l);
            uint32_t a[4];
            a[0] = todd ? t01 : t00;   // (row g,   col tig)
            a[1] = todd ? t11 : t10;   // (row g+8, col tig)
            a[2] = todd ? u01 : u00;   // (row g,   col tig+4)
            a[3] = todd ? u11 : u10;   // (row g+8, col tig+4)
            #pragma unroll
            for (int nt = 0; nt < 8; nt++) {
                uint32_t bf[2];
                bf[0] = __float_as_uint(Vs[ks * 8 + tig][nt * 8 + g]);
                bf[1] = __float_as_uint(Vs[ks * 8 + tig + 4][nt * 8 + g]);
                mma1688(O[nt], a, bf);
            }
        }
    }

    // ---- Epilogue: normalize and store ----
    const float inv0 = 1.f / l0;
    const float inv1 = 1.f / l1;
    float* o0p = att + (size_t)(b * TT + row0) * HH + h * HS;
    float* o1p = att + (size_t)(b * TT + row1) * HH + h * HS;
    #pragma unroll
    for (int nt = 0; nt < 8; nt++) {
        int c = nt * 8 + 2 * tig;
        *(float2*)(o0p + c) = make_float2(O[nt][0] * inv0, O[nt][1] * inv0);
        *(float2*)(o1p + c) = make_float2(O[nt][2] * inv1, O[nt][3] * inv1);
    }
}

// ---------------------------------------------------------------------------
// Launch
// ---------------------------------------------------------------------------
extern "C" void kernel_launch(void* const* d_in, const int* in_sizes, int n_in,
                              void* d_out, int out_size)
{
    const float* x      = (const float*)d_in[0];   // [8,1024,768]
    const float* W_attn = (const float*)d_in[1];   // [768,2304]
    const float* b_attn = (const float*)d_in[2];   // [2304]
    const float* W_proj = (const float*)d_in[3];   // [768,768]
    const float* b_proj = (const float*)d_in[4];   // [768]
    float* out = (float*)d_out;                    // [8,1024,768]

    float* qkv;  cudaGetSymbolAddress((void**)&qkv, g_qkv);
    float* attb; cudaGetSymbolAddress((void**)&attb, g_att);

    // 1) QKV projection: [8192,768] @ [768,2304] + b -> g_qkv  (tf32 mma.sync)
    {
        dim3 grid(H3 / 128, MROWS / 128);
        gemm_mma_kernel<<<grid, 256>>>(x, W_attn, b_attn, qkv, MROWS, H3, HH);
    }
    // 2) Causal attention (tf32 mma.sync flash) -> g_att
    {
        dim3 grid(TT / 64, NH, BB);
        attn_mma_kernel<<<grid, 128>>>(qkv, attb);
    }
    // 3) Output projection: [8192,768] @ [768,768] + b -> out  (tf32 mma.sync)
    {
        dim3 grid(HH / 128, MROWS / 128);
        gemm_mma_kernel<<<grid, 256>>>(attb, W_proj, b_proj, out, MROWS, HH, HH);
    }
}

// round 10
// speedup vs baseline: 3.7385x; 1.3315x over previous
#include <cuda_runtime.h>
#include <cstdint>
#include <math.h>

// Problem constants
#define BB   8
#define TT   1024
#define HH   768
#define NH   12
#define HS   64
#define H3   2304          // 3*H
#define MROWS (BB*TT)      // 8192

// Scratch (device globals — no allocations allowed)
__device__ float g_qkv[(size_t)MROWS * H3];   // [8192, 2304]
__device__ float g_att[(size_t)MROWS * HH];   // [8192, 768]

// ---------------------------------------------------------------------------
// tf32 helpers (arch-generic PTX; NO tcgen05 — harness lowers via compute_103
// which rejects all sm_103a-gated instructions)
// ---------------------------------------------------------------------------
__device__ __forceinline__ float to_tf32(float x) {
    float y;
    asm("cvt.rna.tf32.f32 %0, %1;" : "=f"(y) : "f"(x));
    return y;
}

__device__ __forceinline__ void mma1688(float* d, const uint32_t* a, const uint32_t* b) {
    asm volatile(
        "mma.sync.aligned.m16n8k8.row.col.f32.tf32.tf32.f32 "
        "{%0,%1,%2,%3}, {%4,%5,%6,%7}, {%8,%9}, {%0,%1,%2,%3};"
        : "+f"(d[0]), "+f"(d[1]), "+f"(d[2]), "+f"(d[3])
        : "r"(a[0]), "r"(a[1]), "r"(a[2]), "r"(a[3]),
          "r"(b[0]), "r"(b[1]));
}

// ===========================================================================
// Warp-MMA tf32 GEMM with bias: C[M,N] = A[M,K] @ B[K,N] + bias[N]
// BM=128, BN=128, BK=32, 256 threads = 8 warps (4 m x 2 n), warp tile 32x64.
// Bank-conflict-free fragment layouts:
//   As[m][k] pitch 36 (36 mod 32 = 4): A-frag bank = 4g+tig -> distinct.
//   Bs[k][n] pitch 136 (136 mod 32 = 8): B-frag bank = 8tig+g -> distinct.
// ===========================================================================
#define AP 36    // As row pitch (floats): [128 m][32 k]
#define BP 136   // Bs row pitch (floats): [32 k][128 n]

__global__ __launch_bounds__(256, 2) void gemm_mma_kernel(
    const float* __restrict__ A, const float* __restrict__ B,
    const float* __restrict__ bias, float* __restrict__ C,
    int M, int N, int K)
{
    __shared__ float As[128 * AP];
    __shared__ float Bs[32 * BP];

    const int tid = threadIdx.x;
    const int wid = tid >> 5;
    const int lane = tid & 31;
    const int g   = lane >> 2;
    const int tig = lane & 3;
    const int wm = wid & 3;
    const int wn = wid >> 2;
    const int bm = blockIdx.y * 128;
    const int bn = blockIdx.x * 128;

    float d[2][8][4];
    #pragma unroll
    for (int mt = 0; mt < 2; mt++)
        #pragma unroll
        for (int nt = 0; nt < 8; nt++)
            #pragma unroll
            for (int r = 0; r < 4; r++) d[mt][nt][r] = 0.f;

    const int a_m  = tid >> 3;      // 0..31 (+32 per i)
    const int a_c4 = tid & 7;       // float4 index within 32-float k-row
    const int b_k  = tid >> 5;      // 0..7 (+8 per i)
    const int b_n4 = lane;          // 0..31 float4 index

    const int nit = K >> 5;
    for (int kc = 0; kc < nit; kc++) {
        __syncthreads();
        // A tile: [128 m][32 k] row-major, pitch 36, STS.128 (conflict-free)
        #pragma unroll
        for (int i = 0; i < 4; i++) {
            int m = a_m + i * 32;
            float4 v = *(const float4*)(A + (size_t)(bm + m) * K + kc * 32 + a_c4 * 4);
            float4 w;
            w.x = to_tf32(v.x); w.y = to_tf32(v.y);
            w.z = to_tf32(v.z); w.w = to_tf32(v.w);
            *(float4*)&As[m * AP + a_c4 * 4] = w;
        }
        // B tile: [32 k][128 n], pitch 136, STS.128 (conflict-free)
        #pragma unroll
        for (int i = 0; i < 4; i++) {
            int k = b_k + i * 8;
            float4 v = *(const float4*)(B + (size_t)(kc * 32 + k) * N + bn + b_n4 * 4);
            float4 w;
            w.x = to_tf32(v.x); w.y = to_tf32(v.y);
            w.z = to_tf32(v.z); w.w = to_tf32(v.w);
            *(float4*)&Bs[k * BP + b_n4 * 4] = w;
        }
        __syncthreads();

        #pragma unroll
        for (int ks = 0; ks < 4; ks++) {
            const int k0 = ks * 8;
            // A fragments: A[mrow][k0+tig], bank = 4g+tig (conflict-free)
            uint32_t af[2][4];
            #pragma unroll
            for (int mt = 0; mt < 2; mt++) {
                int mrow = wm * 32 + mt * 16 + g;
                af[mt][0] = __float_as_uint(As[mrow * AP + k0 + tig]);
                af[mt][1] = __float_as_uint(As[(mrow + 8) * AP + k0 + tig]);
                af[mt][2] = __float_as_uint(As[mrow * AP + k0 + tig + 4]);
                af[mt][3] = __float_as_uint(As[(mrow + 8) * AP + k0 + tig + 4]);
            }
            // B fragments: B[k0+tig][ncol], bank = 8tig+g (conflict-free)
            uint32_t bf[8][2];
            #pragma unroll
            for (int nt = 0; nt < 8; nt++) {
                int ncol = wn * 64 + nt * 8 + g;
                bf[nt][0] = __float_as_uint(Bs[(k0 + tig) * BP + ncol]);
                bf[nt][1] = __float_as_uint(Bs[(k0 + tig + 4) * BP + ncol]);
            }
            #pragma unroll
            for (int mt = 0; mt < 2; mt++)
                #pragma unroll
                for (int nt = 0; nt < 8; nt++)
                    mma1688(d[mt][nt], af[mt], bf[nt]);
        }
    }

    // Epilogue: bias add + store
    #pragma unroll
    for (int mt = 0; mt < 2; mt++) {
        int r0 = bm + wm * 32 + mt * 16 + g;
        #pragma unroll
        for (int nt = 0; nt < 8; nt++) {
            int c0 = bn + wn * 64 + nt * 8 + tig * 2;
            float bx = bias[c0], by = bias[c0 + 1];
            float2 o0 = make_float2(d[mt][nt][0] + bx, d[mt][nt][1] + by);
            float2 o1 = make_float2(d[mt][nt][2] + bx, d[mt][nt][3] + by);
            *(float2*)(C + (size_t)r0 * N + c0)       = o0;
            *(float2*)(C + (size_t)(r0 + 8) * N + c0) = o1;
        }
    }
}

// ===========================================================================
// Causal flash attention via tf32 mma.sync.  (unchanged — R9-proven)
// Block = 128 threads (4 warps), Q tile = 64 rows (16/warp), K/V tile = 64.
// grid = (T/64, NH, B). Only kt <= qt tiles; diagonal tile element-masked.
//   Ks pitch 68: B-frag banks 4g+tig (conflict-free); Q stages through Ks.
//   Vs pitch 72: B-frag banks 8tig+g (conflict-free).
// P converted C-layout -> A-layout in-register via shfl (no smem round trip).
// ===========================================================================
#define KP 68
#define VP 72

__global__ __launch_bounds__(128, 3) void attn_mma_kernel(
    const float* __restrict__ qkv, float* __restrict__ att)
{
    __shared__ float Ks[64][KP];   // K tile; also stages Q at start
    __shared__ float Vs[64][VP];   // V tile

    const int tid  = threadIdx.x;
    const int wid  = tid >> 5;
    const int lane = tid & 31;
    const int g    = lane >> 2;
    const int tig  = lane & 3;
    const int b    = blockIdx.z;
    const int h    = blockIdx.y;
    const int qt   = blockIdx.x;        // q tile index 0..15
    const int qs   = qt * 64;

    // ---- Stage Q tile (scaled by 1/8, tf32-rounded) into Ks buffer ----
    {
        const float* qb = qkv + (size_t)(b * TT + qs) * H3 + h * HS;
        #pragma unroll
        for (int i = 0; i < 8; i++) {
            int idx = tid + i * 128;
            int r = idx >> 4, c4 = idx & 15;
            float4 v = *(const float4*)(qb + (size_t)r * H3 + c4 * 4);
            float4 w;
            w.x = to_tf32(v.x * 0.125f); w.y = to_tf32(v.y * 0.125f);
            w.z = to_tf32(v.z * 0.125f); w.w = to_tf32(v.w * 0.125f);
            *(float4*)&Ks[r][c4 * 4] = w;
        }
    }
    __syncthreads();

    // ---- Extract Q fragments to registers (A-layout, m16k8 per k-step) ----
    uint32_t af[8][4];
    {
        const int r0 = wid * 16 + g;
        #pragma unroll
        for (int ks = 0; ks < 8; ks++) {
            af[ks][0] = __float_as_uint(Ks[r0][ks * 8 + tig]);
            af[ks][1] = __float_as_uint(Ks[r0 + 8][ks * 8 + tig]);
            af[ks][2] = __float_as_uint(Ks[r0][ks * 8 + tig + 4]);
            af[ks][3] = __float_as_uint(Ks[r0 + 8][ks * 8 + tig + 4]);
        }
    }

    float O[8][4];
    #pragma unroll
    for (int nt = 0; nt < 8; nt++)
        #pragma unroll
        for (int r = 0; r < 4; r++) O[nt][r] = 0.f;
    float m0 = -INFINITY, m1 = -INFINITY, l0 = 0.f, l1 = 0.f;
    const int row0 = qs + wid * 16 + g;     // global q rows this thread owns
    const int row1 = row0 + 8;

    const int s0l = (lane & ~3) | (tig >> 1);   // shfl source lanes for P conversion
    const int s1l = s0l + 2;
    const bool todd = (tig & 1);

    for (int kt = 0; kt <= qt; kt++) {
        __syncthreads();    // prior compute / Q extraction done before overwrite
        // ---- Stage K and V tiles (tf32-rounded) ----
        const float* kb = qkv + (size_t)(b * TT + kt * 64) * H3 + HH + h * HS;
        const float* vb = kb + HH;
        #pragma unroll
        for (int i = 0; i < 8; i++) {
            int idx = tid + i * 128;
            int r = idx >> 4, c4 = idx & 15;
            float4 v = *(const float4*)(kb + (size_t)r * H3 + c4 * 4);
            float4 w;
            w.x = to_tf32(v.x); w.y = to_tf32(v.y);
            w.z = to_tf32(v.z); w.w = to_tf32(v.w);
            *(float4*)&Ks[r][c4 * 4] = w;
            float4 u = *(const float4*)(vb + (size_t)r * H3 + c4 * 4);
            float4 z;
            z.x = to_tf32(u.x); z.y = to_tf32(u.y);
            z.z = to_tf32(u.z); z.w = to_tf32(u.w);
            *(float4*)&Vs[r][c4 * 4] = z;
        }
        __syncthreads();

        // ---- S = Q @ K^T  (16 rows x 64 keys per warp) ----
        float S[8][4];
        #pragma unroll
        for (int nt = 0; nt < 8; nt++)
            #pragma unroll
            for (int r = 0; r < 4; r++) S[nt][r] = 0.f;
        #pragma unroll
        for (int ks = 0; ks < 8; ks++) {
            #pragma unroll
            for (int nt = 0; nt < 8; nt++) {
                uint32_t bf[2];
                bf[0] = __float_as_uint(Ks[nt * 8 + g][ks * 8 + tig]);
                bf[1] = __float_as_uint(Ks[nt * 8 + g][ks * 8 + tig + 4]);
                mma1688(S[nt], af[ks], bf);
            }
        }

        // ---- Causal mask (diagonal tile only) ----
        if (kt == qt) {
            #pragma unroll
            for (int nt = 0; nt < 8; nt++) {
                int c0 = kt * 64 + nt * 8 + 2 * tig;
                if (c0     > row0) S[nt][0] = -INFINITY;
                if (c0 + 1 > row0) S[nt][1] = -INFINITY;
                if (c0     > row1) S[nt][2] = -INFINITY;
                if (c0 + 1 > row1) S[nt][3] = -INFINITY;
            }
        }

        // ---- Online softmax ----
        float tm0 = -INFINITY, tm1 = -INFINITY;
        #pragma unroll
        for (int nt = 0; nt < 8; nt++) {
            tm0 = fmaxf(tm0, fmaxf(S[nt][0], S[nt][1]));
            tm1 = fmaxf(tm1, fmaxf(S[nt][2], S[nt][3]));
        }
        tm0 = fmaxf(tm0, __shfl_xor_sync(0xffffffffu, tm0, 1));
        tm0 = fmaxf(tm0, __shfl_xor_sync(0xffffffffu, tm0, 2));
        tm1 = fmaxf(tm1, __shfl_xor_sync(0xffffffffu, tm1, 1));
        tm1 = fmaxf(tm1, __shfl_xor_sync(0xffffffffu, tm1, 2));

        float mn0 = fmaxf(m0, tm0), mn1 = fmaxf(m1, tm1);
        float al0 = __expf(m0 - mn0), al1 = __expf(m1 - mn1);
        m0 = mn0; m1 = mn1;

        float rs0 = 0.f, rs1 = 0.f;
        uint32_t P[8][4];
        #pragma unroll
        for (int nt = 0; nt < 8; nt++) {
            float p0 = __expf(S[nt][0] - mn0);
            float p1 = __expf(S[nt][1] - mn0);
            float p2 = __expf(S[nt][2] - mn1);
            float p3 = __expf(S[nt][3] - mn1);
            rs0 += p0 + p1;
            rs1 += p2 + p3;
            P[nt][0] = __float_as_uint(to_tf32(p0));
            P[nt][1] = __float_as_uint(to_tf32(p1));
            P[nt][2] = __float_as_uint(to_tf32(p2));
            P[nt][3] = __float_as_uint(to_tf32(p3));
        }
        rs0 += __shfl_xor_sync(0xffffffffu, rs0, 1);
        rs0 += __shfl_xor_sync(0xffffffffu, rs0, 2);
        rs1 += __shfl_xor_sync(0xffffffffu, rs1, 1);
        rs1 += __shfl_xor_sync(0xffffffffu, rs1, 2);
        l0 = l0 * al0 + rs0;
        l1 = l1 * al1 + rs1;

        #pragma unroll
        for (int nt = 0; nt < 8; nt++) {
            O[nt][0] *= al0; O[nt][1] *= al0;
            O[nt][2] *= al1; O[nt][3] *= al1;
        }

        // ---- O += P @ V ----
        #pragma unroll
        for (int ks = 0; ks < 8; ks++) {
            // Convert P C-layout (cols 2tig,2tig+1) -> A-layout (cols tig,tig+4)
            uint32_t t00 = __shfl_sync(0xffffffffu, P[ks][0], s0l);
            uint32_t t01 = __shfl_sync(0xffffffffu, P[ks][1], s0l);
            uint32_t t10 = __shfl_sync(0xffffffffu, P[ks][2], s0l);
            uint32_t t11 = __shfl_sync(0xffffffffu, P[ks][3], s0l);
            uint32_t u00 = __shfl_sync(0xffffffffu, P[ks][0], s1l);
            uint32_t u01 = __shfl_sync(0xffffffffu, P[ks][1], s1l);
            uint32_t u10 = __shfl_sync(0xffffffffu, P[ks][2], s1l);
            uint32_t u11 = __shfl_sync(0xffffffffu, P[ks][3], s1l);
            uint32_t a[4];
            a[0] = todd ? t01 : t00;   // (row g,   col tig)
            a[1] = todd ? t11 : t10;   // (row g+8, col tig)
            a[2] = todd ? u01 : u00;   // (row g,   col tig+4)
            a[3] = todd ? u11 : u10;   // (row g+8, col tig+4)
            #pragma unroll
            for (int nt = 0; nt < 8; nt++) {
                uint32_t bf[2];
                bf[0] = __float_as_uint(Vs[ks * 8 + tig][nt * 8 + g]);
                bf[1] = __float_as_uint(Vs[ks * 8 + tig + 4][nt * 8 + g]);
                mma1688(O[nt], a, bf);
            }
        }
    }

    // ---- Epilogue: normalize and store ----
    const float inv0 = 1.f / l0;
    const float inv1 = 1.f / l1;
    float* o0p = att + (size_t)(b * TT + row0) * HH + h * HS;
    float* o1p = att + (size_t)(b * TT + row1) * HH + h * HS;
    #pragma unroll
    for (int nt = 0; nt < 8; nt++) {
        int c = nt * 8 + 2 * tig;
        *(float2*)(o0p + c) = make_float2(O[nt][0] * inv0, O[nt][1] * inv0);
        *(float2*)(o1p + c) = make_float2(O[nt][2] * inv1, O[nt][3] * inv1);
    }
}

// ---------------------------------------------------------------------------
// Launch
// ---------------------------------------------------------------------------
extern "C" void kernel_launch(void* const* d_in, const int* in_sizes, int n_in,
                              void* d_out, int out_size)
{
    const float* x      = (const float*)d_in[0];   // [8,1024,768]
    const float* W_attn = (const float*)d_in[1];   // [768,2304]
    const float* b_attn = (const float*)d_in[2];   // [2304]
    const float* W_proj = (const float*)d_in[3];   // [768,768]
    const float* b_proj = (const float*)d_in[4];   // [768]
    float* out = (float*)d_out;                    // [8,1024,768]

    float* qkv;  cudaGetSymbolAddress((void**)&qkv, g_qkv);
    float* attb; cudaGetSymbolAddress((void**)&attb, g_att);

    // 1) QKV projection: [8192,768] @ [768,2304] + b -> g_qkv  (tf32 mma.sync)
    {
        dim3 grid(H3 / 128, MROWS / 128);
        gemm_mma_kernel<<<grid, 256>>>(x, W_attn, b_attn, qkv, MROWS, H3, HH);
    }
    // 2) Causal attention (tf32 mma.sync flash) -> g_att
    {
        dim3 grid(TT / 64, NH, BB);
        attn_mma_kernel<<<grid, 128>>>(qkv, attb);
    }
    // 3) Output projection: [8192,768] @ [768,768] + b -> out  (tf32 mma.sync)
    {
        dim3 grid(HH / 128, MROWS / 128);
        gemm_mma_kernel<<<grid, 256>>>(attb, W_proj, b_proj, out, MROWS, HH, HH);
    }
}